// round 14
// baseline (speedup 1.0000x reference)
#include <cuda_runtime.h>

#define NB 26
#define POSE_F 78        // 26*3 floats per pose
#define TPB 32           // one warp per block; thread t owns poses t and t+32
#define PPB 64           // poses per block

// Per-bone 8-float constant record: [r0,r1,r2,r3] [r4, lx,ly,lz]
// (r0..r4 = the 5 needed R_ref entries m00,m10,m20,m21,m22)
__device__ float4 g_tab4[NB * 2];
__constant__ float4 c_tab4[NB * 2];

// ---------- packed f32x2 primitives (PTX-only on sm_100a) ----------
typedef unsigned long long f2;

__device__ __forceinline__ f2 pk2(float lo, float hi) {
    f2 r; asm("mov.b64 %0, {%1, %2};" : "=l"(r) : "f"(lo), "f"(hi)); return r;
}
__device__ __forceinline__ void upk2(f2 p, float& lo, float& hi) {
    asm("mov.b64 {%0, %1}, %2;" : "=f"(lo), "=f"(hi) : "l"(p));
}
__device__ __forceinline__ f2 fma2_(f2 a, f2 b, f2 c) {
    f2 r; asm("fma.rn.f32x2 %0, %1, %2, %3;" : "=l"(r) : "l"(a), "l"(b), "l"(c)); return r;
}
__device__ __forceinline__ f2 mul2_(f2 a, f2 b) {
    f2 r; asm("mul.rn.f32x2 %0, %1, %2;" : "=l"(r) : "l"(a), "l"(b)); return r;
}
__device__ __forceinline__ f2 add2_(f2 a, f2 b) {
    f2 r; asm("add.rn.f32x2 %0, %1, %2;" : "=l"(r) : "l"(a), "l"(b)); return r;
}

struct M3p { f2 a[9]; };   // a[6] holds R20 = -SY convention where noted
struct V3p { f2 v[3]; };

// ---------- per-lane scalar trig + normalize (MUFU section) ----------
__device__ __forceinline__ void lane_math(float ez, float ey, float ex,
                                          float4 q0, float r4,
                                          float& CZ, float& SZ, float& SY,
                                          float& CY, float& CX, float& SX)
{
    float sz, cz, sy, cy, sx, cx;
    __sincosf(ez, &sz, &cz);
    __sincosf(ey, &sy, &cy);
    __sincosf(ex, &sx, &cx);
    float M00 = q0.x * (cz * cy);
    float M10 = q0.y * (sz * cy);
    SY        = q0.z * sy;            // = -M20  (q0.z = -sy_ref)
    float M21 = q0.w * (cy * sx);
    float M22 = r4   * (cy * cx);
    float i0 = rsqrtf(fmaxf(fmaf(M00, M00, M10 * M10), 1e-30f));
    CZ = M00 * i0;  SZ = M10 * i0;
    float t = fmaxf(fmaf(-SY, SY, 1.0f), 1e-30f);
    CY = t * rsqrtf(t);               // sqrt(t), approx
    float i2 = rsqrtf(fmaxf(fmaf(M21, M21, M22 * M22), 1e-30f));
    CX = M22 * i2;  SX = M21 * i2;
}

// Build packed rotation (R20 returned as nSY; callers use it directly).
__device__ __forceinline__ void buildRp(float ez0, float ey0, float ex0,
                                        float ez1, float ey1, float ex1,
                                        float4 q0, float r4,
                                        f2& R00, f2& R01, f2& R02,
                                        f2& R10, f2& R11, f2& R12,
                                        f2& nSY, f2& R21, f2& R22)
{
    float CZ0,SZ0,SY0,CY0,CX0,SX0, CZ1,SZ1,SY1,CY1,CX1,SX1;
    lane_math(ez0, ey0, ex0, q0, r4, CZ0, SZ0, SY0, CY0, CX0, SX0);
    lane_math(ez1, ey1, ex1, q0, r4, CZ1, SZ1, SY1, CY1, CX1, SX1);

    f2 CZ  = pk2(CZ0, CZ1),   SZ  = pk2(SZ0, SZ1),   SY = pk2(SY0, SY1);
    f2 CY  = pk2(CY0, CY1),   CX  = pk2(CX0, CX1),   SX = pk2(SX0, SX1);
    f2 nSZ = pk2(-SZ0, -SZ1), nCZ = pk2(-CZ0, -CZ1);
    nSY = pk2(-SY0, -SY1);

    f2 czsy = mul2_(CZ, SY), szsy = mul2_(SZ, SY);
    R00 = mul2_(CZ, CY);
    R01 = fma2_(czsy, SX, mul2_(nSZ, CX));
    R02 = fma2_(czsy, CX, mul2_(SZ, SX));
    R10 = mul2_(SZ, CY);
    R11 = fma2_(szsy, SX, mul2_(CZ, CX));
    R12 = fma2_(szsy, CX, mul2_(nCZ, SX));
    R21 = mul2_(CY, SX);
    R22 = mul2_(CY, CX);
}

// Full bone step, both poses packed. Ap/bp by value (aliasing-safe, SSA-free).
__device__ __forceinline__ void fullstep(int bone, M3p Ap, V3p bp,
                                         M3p& Ao, V3p& bo,
                                         float* __restrict__ P0,
                                         float* __restrict__ P1)
{
    const float4 q0 = c_tab4[2 * bone];
    const float4 q1 = c_tab4[2 * bone + 1];
    const f2 lx = pk2(q1.y, q1.y);
    const f2 ly = pk2(q1.z, q1.z);
    const f2 lz = pk2(q1.w, q1.w);

    // abs_loc = l . Ap + bp
    f2 ax = fma2_(lx, Ap.a[0], fma2_(ly, Ap.a[3], fma2_(lz, Ap.a[6], bp.v[0])));
    f2 ay = fma2_(lx, Ap.a[1], fma2_(ly, Ap.a[4], fma2_(lz, Ap.a[7], bp.v[1])));
    f2 az = fma2_(lx, Ap.a[2], fma2_(ly, Ap.a[5], fma2_(lz, Ap.a[8], bp.v[2])));

    const int o = bone * 3;
    float ez0 = P0[o], ey0 = P0[o + 1], ex0 = P0[o + 2];
    float ez1 = P1[o], ey1 = P1[o + 1], ex1 = P1[o + 2];
    { float u, v; upk2(ax, u, v); P0[o]     = u; P1[o]     = v; }
    { float u, v; upk2(ay, u, v); P0[o + 1] = u; P1[o + 1] = v; }
    { float u, v; upk2(az, u, v); P0[o + 2] = u; P1[o + 2] = v; }

    f2 R00, R01, R02, R10, R11, R12, nSY, R21, R22;
    buildRp(ez0, ey0, ex0, ez1, ey1, ex1, q0, q1.x,
            R00, R01, R02, R10, R11, R12, nSY, R21, R22);

    #pragma unroll
    for (int k = 0; k < 3; k++) {
        f2 a0 = Ap.a[3 * k], a1 = Ap.a[3 * k + 1], a2 = Ap.a[3 * k + 2];
        Ao.a[3 * k + 0] = fma2_(a0, R00, fma2_(a1, R10, mul2_(a2, nSY)));
        Ao.a[3 * k + 1] = fma2_(a0, R01, fma2_(a1, R11, mul2_(a2, R21)));
        Ao.a[3 * k + 2] = fma2_(a0, R02, fma2_(a1, R12, mul2_(a2, R22)));
    }
    f2 tx = add2_(bp.v[0], lx), ty = add2_(bp.v[1], ly), tz = add2_(bp.v[2], lz);
    bo.v[0] = fma2_(tx, R00, fma2_(ty, R10, mul2_(tz, nSY)));
    bo.v[1] = fma2_(tx, R01, fma2_(ty, R11, mul2_(tz, R21)));
    bo.v[2] = fma2_(tx, R02, fma2_(ty, R12, mul2_(tz, R22)));
}

// Root bone (parent = identity): A0 = R, b0 = l.R, abs0 = l (exact).
__device__ __forceinline__ void rootstep(M3p& Ao, V3p& bo,
                                         float* __restrict__ P0,
                                         float* __restrict__ P1)
{
    const float4 q0 = c_tab4[0];
    const float4 q1 = c_tab4[1];
    float ez0 = P0[0], ey0 = P0[1], ex0 = P0[2];
    float ez1 = P1[0], ey1 = P1[1], ex1 = P1[2];
    P0[0] = q1.y; P0[1] = q1.z; P0[2] = q1.w;
    P1[0] = q1.y; P1[1] = q1.z; P1[2] = q1.w;

    f2 R00, R01, R02, R10, R11, R12, nSY, R21, R22;
    buildRp(ez0, ey0, ex0, ez1, ey1, ex1, q0, q1.x,
            R00, R01, R02, R10, R11, R12, nSY, R21, R22);

    Ao.a[0] = R00; Ao.a[1] = R01; Ao.a[2] = R02;
    Ao.a[3] = R10; Ao.a[4] = R11; Ao.a[5] = R12;
    Ao.a[6] = nSY; Ao.a[7] = R21; Ao.a[8] = R22;

    f2 lx = pk2(q1.y, q1.y), ly = pk2(q1.z, q1.z), lz = pk2(q1.w, q1.w);
    bo.v[0] = fma2_(lx, R00, fma2_(ly, R10, mul2_(lz, nSY)));
    bo.v[1] = fma2_(lx, R01, fma2_(ly, R11, mul2_(lz, R21)));
    bo.v[2] = fma2_(lx, R02, fma2_(ly, R12, mul2_(lz, R22)));
}

__device__ __forceinline__ void leafstep(int bone, const M3p& A, const V3p& b,
                                         float* __restrict__ P0,
                                         float* __restrict__ P1)
{
    const float4 q1 = c_tab4[2 * bone + 1];
    f2 lx = pk2(q1.y, q1.y), ly = pk2(q1.z, q1.z), lz = pk2(q1.w, q1.w);
    f2 ax = fma2_(lx, A.a[0], fma2_(ly, A.a[3], fma2_(lz, A.a[6], b.v[0])));
    f2 ay = fma2_(lx, A.a[1], fma2_(ly, A.a[4], fma2_(lz, A.a[7], b.v[1])));
    f2 az = fma2_(lx, A.a[2], fma2_(ly, A.a[5], fma2_(lz, A.a[8], b.v[2])));
    const int o = bone * 3;
    { float u, v; upk2(ax, u, v); P0[o]     = u; P1[o]     = v; }
    { float u, v; upk2(ay, u, v); P0[o + 1] = u; P1[o + 1] = v; }
    { float u, v; upk2(az, u, v); P0[o + 2] = u; P1[o + 2] = v; }
}

// Pre-kernel: accurate trig for the 26 reference rotations, 8-float records.
__global__ void ref_table_kernel(const float* __restrict__ rel_rot_ref,
                                 const float* __restrict__ rel_loc)
{
    int i = threadIdx.x;
    if (i < NB) {
        float ez = rel_rot_ref[i * 3 + 0];
        float ey = rel_rot_ref[i * 3 + 1];
        float ex = rel_rot_ref[i * 3 + 2];
        float sz, cz, sy, cy, sx, cx;
        sincosf(ez, &sz, &cz);
        sincosf(ey, &sy, &cy);
        sincosf(ex, &sx, &cx);
        g_tab4[2 * i]     = make_float4(cz * cy, sz * cy, -sy, cy * sx);
        g_tab4[2 * i + 1] = make_float4(cy * cx,
                                        rel_loc[3 * i + 0],
                                        rel_loc[3 * i + 1],
                                        rel_loc[3 * i + 2]);
    }
}

__global__ void __launch_bounds__(TPB, 11)
fk_kernel(const float* __restrict__ x,
          float* __restrict__ out)
{
    __shared__ float pose[PPB * POSE_F];   // 19968 B

    const int tid = threadIdx.x;

    // Proven float4 staging pattern (64 poses, 1248 float4 over 32 threads).
    const int NV4 = PPB * POSE_F / 4;      // 1248, divides evenly by 32
    const float4* gin = reinterpret_cast<const float4*>(x) + (size_t)blockIdx.x * NV4;
    float4* sp4 = reinterpret_cast<float4*>(pose);
    #pragma unroll 4
    for (int i = tid; i < NV4; i += TPB) sp4[i] = gin[i];
    __syncthreads();

    float* P0 = pose + tid * POSE_F;
    float* P1 = pose + (tid + TPB) * POSE_F;

    M3p A, Asv; V3p b, bsv;

    rootstep(A, b, P0, P1);                      // bone 0
    fullstep(1, A, b, Asv, bsv, P0, P1);         // Asv = A1

    fullstep(15, Asv, bsv, A, b, P0, P1);
    fullstep(16, A, b, A, b, P0, P1);
    fullstep(17, A, b, A, b, P0, P1);
    leafstep(18, A, b, P0, P1);
    fullstep(19, Asv, bsv, A, b, P0, P1);
    fullstep(20, A, b, A, b, P0, P1);
    fullstep(21, A, b, A, b, P0, P1);
    leafstep(22, A, b, P0, P1);

    fullstep(2, Asv, bsv, A, b, P0, P1);
    fullstep(3, A, b, A, b, P0, P1);
    fullstep(4, A, b, Asv, bsv, P0, P1);         // Asv = A4

    fullstep(7, Asv, bsv, A, b, P0, P1);
    fullstep(8, A, b, A, b, P0, P1);
    fullstep(9, A, b, A, b, P0, P1);
    leafstep(10, A, b, P0, P1);
    fullstep(11, Asv, bsv, A, b, P0, P1);
    fullstep(12, A, b, A, b, P0, P1);
    fullstep(13, A, b, A, b, P0, P1);
    leafstep(14, A, b, P0, P1);

    fullstep(5, Asv, bsv, A, b, P0, P1);
    fullstep(6, A, b, A, b, P0, P1);
    leafstep(23, A, b, P0, P1);
    leafstep(24, A, b, P0, P1);
    leafstep(25, A, b, P0, P1);

    __syncthreads();

    float4* gout = reinterpret_cast<float4*>(out) + (size_t)blockIdx.x * NV4;
    #pragma unroll 4
    for (int i = tid; i < NV4; i += TPB) gout[i] = sp4[i];
}

extern "C" void kernel_launch(void* const* d_in, const int* in_sizes, int n_in,
                              void* d_out, int out_size)
{
    const float* x           = (const float*)d_in[0];  // (131072, 26, 3)
    const float* rel_loc     = (const float*)d_in[1];  // (26, 3)
    const float* rel_rot_ref = (const float*)d_in[2];  // (26, 3)
    float* out               = (float*)d_out;          // (131072, 26, 3)

    const int batch = in_sizes[0] / POSE_F;            // 131072

    ref_table_kernel<<<1, 32>>>(rel_rot_ref, rel_loc);

    void* g_tab_ptr = nullptr;
    cudaGetSymbolAddress(&g_tab_ptr, g_tab4);
    cudaMemcpyToSymbolAsync(c_tab4, g_tab_ptr, sizeof(float4) * NB * 2, 0,
                            cudaMemcpyDeviceToDevice, 0);

    fk_kernel<<<batch / PPB, TPB>>>(x, out);
}

// round 16
// speedup vs baseline: 1.4359x; 1.4359x over previous
#include <cuda_runtime.h>

#define NB 26
#define POSE_F 78        // 26*3 floats per pose
#define TPB 64
#define BATCH 131072

struct M3 { float a[9]; };
struct V3 { float v[3]; };

__device__ __forceinline__ float fsqrt_approx(float t) {
    t = fmaxf(t, 1e-30f);
    return t * rsqrtf(t);
}

// INDEPENDENT half: angles -> rebuilt rotation R. No chain dependency.
// tab[2*bone] = (m00_ref, m10_ref, -sy_ref, m21_ref); tab[2*bone+1].x = m22_ref.
__device__ __forceinline__ void buildR(int bone, const float* __restrict__ P,
                                       const float4* __restrict__ tab,
                                       float R[9])
{
    float ez = P[bone * 3 + 0];
    float ey = P[bone * 3 + 1];
    float ex = P[bone * 3 + 2];

    float sz, cz, sy, cy, sx, cx;
    __sincosf(ez, &sz, &cz);
    __sincosf(ey, &sy, &cy);
    __sincosf(ex, &sx, &cx);

    const float4 q0 = tab[2 * bone];
    const float  r4 = tab[2 * bone + 1].x;

    // 5 needed entries of M = R_ref (hadamard) R_chg
    float M00 = q0.x * (cz * cy);
    float M10 = q0.y * (sz * cy);
    // SY = -M20 = -(m20_ref * m20_chg) = -((-sy_ref)(-sy)) = (-sy_ref)*sy = q0.z*sy
    float SY  = q0.z * sy;
    float M21 = q0.w * (cy * sx);
    float M22 = r4   * (cy * cx);

    // Trig-free euler->matrix rebuild
    float i0 = rsqrtf(fmaxf(fmaf(M00, M00, M10 * M10), 1e-30f));
    float CZ = M00 * i0, SZ = M10 * i0;
    float CY = fsqrt_approx(fmaf(-SY, SY, 1.0f));
    float i2 = rsqrtf(fmaxf(fmaf(M21, M21, M22 * M22), 1e-30f));
    float CX = M22 * i2, SX = M21 * i2;

    float czsy = CZ * SY, szsy = SZ * SY;
    R[0] = CZ * CY;
    R[1] = czsy * SX - SZ * CX;
    R[2] = czsy * CX + SZ * SX;
    R[3] = SZ * CY;
    R[4] = szsy * SX + CZ * CX;
    R[5] = szsy * CX - CZ * SX;
    R[6] = -SY;
    R[7] = CY * SX;
    R[8] = CY * CX;
}

// DEPENDENT half: abs_loc + A/b chain update using a prebuilt R.
// Ao/bo distinct from Ap/bp at every call site.
__device__ __forceinline__ void chain(int bone, const float R[9],
                                      const float4* __restrict__ tab,
                                      const M3& Ap, const V3& bp,
                                      M3& Ao, V3& bo, float* __restrict__ P)
{
    const float4 q1 = tab[2 * bone + 1];
    const float lx = q1.y, ly = q1.z, lz = q1.w;

    P[bone * 3 + 0] = lx * Ap.a[0] + ly * Ap.a[3] + lz * Ap.a[6] + bp.v[0];
    P[bone * 3 + 1] = lx * Ap.a[1] + ly * Ap.a[4] + lz * Ap.a[7] + bp.v[1];
    P[bone * 3 + 2] = lx * Ap.a[2] + ly * Ap.a[5] + lz * Ap.a[8] + bp.v[2];

    #pragma unroll
    for (int k = 0; k < 3; k++) {
        float a0 = Ap.a[3 * k + 0], a1 = Ap.a[3 * k + 1], a2 = Ap.a[3 * k + 2];
        Ao.a[3 * k + 0] = a0 * R[0] + a1 * R[3] + a2 * R[6];
        Ao.a[3 * k + 1] = a0 * R[1] + a1 * R[4] + a2 * R[7];
        Ao.a[3 * k + 2] = a0 * R[2] + a1 * R[5] + a2 * R[8];
    }
    float tx = bp.v[0] + lx, ty = bp.v[1] + ly, tz = bp.v[2] + lz;
    bo.v[0] = tx * R[0] + ty * R[3] + tz * R[6];
    bo.v[1] = tx * R[1] + ty * R[4] + tz * R[7];
    bo.v[2] = tx * R[2] + ty * R[5] + tz * R[8];
}

__device__ __forceinline__ void leafstep(int bone,
                                         const float4* __restrict__ tab,
                                         const M3& Ap, const V3& bp,
                                         float* __restrict__ P)
{
    const float4 q1 = tab[2 * bone + 1];
    const float lx = q1.y, ly = q1.z, lz = q1.w;
    P[bone * 3 + 0] = lx * Ap.a[0] + ly * Ap.a[3] + lz * Ap.a[6] + bp.v[0];
    P[bone * 3 + 1] = lx * Ap.a[1] + ly * Ap.a[4] + lz * Ap.a[7] + bp.v[1];
    P[bone * 3 + 2] = lx * Ap.a[2] + ly * Ap.a[5] + lz * Ap.a[8] + bp.v[2];
}

__global__ void __launch_bounds__(TPB, 10)
fk_kernel(const float* __restrict__ x,
          const float* __restrict__ rel_loc,
          const float* __restrict__ rel_rot_ref,
          float* __restrict__ out)
{
    __shared__ float pose[TPB * POSE_F];     // 19968 B
    __shared__ float4 tab[NB * 2];           //   832 B

    const int tid = threadIdx.x;

    // In-block reference table: 26 threads, fast trig (error ~2e-7, well in margin).
    // Overlaps with the staging loads below; visible after the __syncthreads.
    if (tid < NB) {
        float ez = rel_rot_ref[tid * 3 + 0];
        float ey = rel_rot_ref[tid * 3 + 1];
        float ex = rel_rot_ref[tid * 3 + 2];
        float sz, cz, sy, cy, sx, cx;
        __sincosf(ez, &sz, &cz);
        __sincosf(ey, &sy, &cy);
        __sincosf(ex, &sx, &cx);
        tab[2 * tid]     = make_float4(cz * cy, sz * cy, -sy, cy * sx);
        tab[2 * tid + 1] = make_float4(cy * cx,
                                       rel_loc[3 * tid + 0],
                                       rel_loc[3 * tid + 1],
                                       rel_loc[3 * tid + 2]);
    }

    const int NV4 = TPB * POSE_F / 4;                 // 1248
    const int NIT = (NV4 + TPB - 1) / TPB;            // 20
    const float4* gin = reinterpret_cast<const float4*>(x) + (size_t)blockIdx.x * NV4;
    float4* sp4 = reinterpret_cast<float4*>(pose);
    #pragma unroll
    for (int i = 0; i < NIT; i++) {
        int idx = tid + i * TPB;
        if (idx < NV4) sp4[idx] = gin[idx];
    }
    __syncthreads();

    float* P = pose + tid * POSE_F;

    M3 S, T, U, V;
    V3 sb, tb, ub, vb;
    float Ra[9], Rb[9];

    // Depth-2 software pipeline: buildR(next bone) interleaved with chain(current).
    {
        M3 I; V3 z;
        I.a[0]=1.f; I.a[1]=0.f; I.a[2]=0.f;
        I.a[3]=0.f; I.a[4]=1.f; I.a[5]=0.f;
        I.a[6]=0.f; I.a[7]=0.f; I.a[8]=1.f;
        z.v[0]=0.f; z.v[1]=0.f; z.v[2]=0.f;

        buildR(0, P, tab, Ra);
        buildR(1, P, tab, Rb);    chain(0,  Ra, tab, I, z,  S, sb, P);   // S = A0
    }
    buildR(15, P, tab, Ra);   chain(1,  Rb, tab, S, sb, T, tb, P);       // T = A1
    buildR(19, P, tab, Rb);   chain(15, Ra, tab, T, tb, U, ub, P);       // U = chain-a
    buildR(2,  P, tab, Ra);   chain(19, Rb, tab, T, tb, V, vb, P);       // V = chain-b
    buildR(16, P, tab, Rb);   chain(2,  Ra, tab, T, tb, S, sb, P);       // S = A2
    buildR(20, P, tab, Ra);   chain(16, Rb, tab, U, ub, T, tb, P);       // T = chain-a
    buildR(3,  P, tab, Rb);   chain(20, Ra, tab, V, vb, U, ub, P);       // U = chain-b
    buildR(17, P, tab, Ra);   chain(3,  Rb, tab, S, sb, V, vb, P);       // V = A3
    buildR(21, P, tab, Rb);   chain(17, Ra, tab, T, tb, S, sb, P);       // S = chain-a
    buildR(4,  P, tab, Ra);   chain(21, Rb, tab, U, ub, T, tb, P);       // T = chain-b
    buildR(7,  P, tab, Rb);   chain(4,  Ra, tab, V, vb, U, ub, P);       // U = A4

    leafstep(18, tab, S, sb, P);    // chain-a end
    leafstep(22, tab, T, tb, P);    // chain-b end

    buildR(11, P, tab, Ra);   chain(7,  Rb, tab, U, ub, S, sb, P);       // S = chain-a
    buildR(5,  P, tab, Rb);   chain(11, Ra, tab, U, ub, T, tb, P);       // T = chain-b
    buildR(8,  P, tab, Ra);   chain(5,  Rb, tab, U, ub, V, vb, P);       // V = A5
    buildR(12, P, tab, Rb);   chain(8,  Ra, tab, S, sb, U, ub, P);       // U = chain-a
    buildR(6,  P, tab, Ra);   chain(12, Rb, tab, T, tb, S, sb, P);       // S = chain-b
    buildR(9,  P, tab, Rb);   chain(6,  Ra, tab, V, vb, T, tb, P);       // T = A6
    buildR(13, P, tab, Ra);   chain(9,  Rb, tab, U, ub, V, vb, P);       // V = chain-a
                              chain(13, Ra, tab, S, sb, U, ub, P);       // U = chain-b

    leafstep(10, tab, V, vb, P);
    leafstep(14, tab, U, ub, P);
    leafstep(23, tab, T, tb, P);
    leafstep(24, tab, T, tb, P);
    leafstep(25, tab, T, tb, P);

    __syncthreads();

    float4* gout = reinterpret_cast<float4*>(out) + (size_t)blockIdx.x * NV4;
    #pragma unroll
    for (int i = 0; i < NIT; i++) {
        int idx = tid + i * TPB;
        if (idx < NV4) gout[idx] = sp4[idx];
    }
}

extern "C" void kernel_launch(void* const* d_in, const int* in_sizes, int n_in,
                              void* d_out, int out_size)
{
    const float* x           = (const float*)d_in[0];  // (131072, 26, 3)
    const float* rel_loc     = (const float*)d_in[1];  // (26, 3)
    const float* rel_rot_ref = (const float*)d_in[2];  // (26, 3)
    float* out               = (float*)d_out;          // (131072, 26, 3)

    const int batch = in_sizes[0] / POSE_F;            // 131072

    // Single-node graph: no pre-kernel, no memcpy.
    fk_kernel<<<batch / TPB, TPB>>>(x, rel_loc, rel_rot_ref, out);
}